// round 10
// baseline (speedup 1.0000x reference)
#include <cuda_runtime.h>

// HysteresisThresholding 2048x2048. Single persistent kernel, 2 blocks/SM
// (7-row bands, ~293 blocks) for ~2x warp occupancy:
//  phase 1: thresholds (low/high) + word-packed weak/strong masks
//  phase 2: band-local smem flood fill to fixed point; flag-array grid
//           barrier with embedded any-changed bit
//  phase 3: final = active ? thin : 0 (thin re-read from L2)

#define H_IMG 2048
#define W_IMG 2048
#define WX 64
#define QX 512
#define N_WORDS (H_IMG * WX)
#define N_PIX (H_IMG * W_IMG)
#define LOW_T 0.3f
#define HIGH_T 0.7f
#define MAX_PASS 64
#define MAX_ROWS 14
#define NT 1024

__device__ unsigned g_active[N_WORDS];
__device__ volatile unsigned g_arrive[512];
__device__ volatile unsigned g_release;

__global__ void __launch_bounds__(NT, 2)
hyst_kernel(const float4* __restrict__ thin4, float* __restrict__ out,
            int rows_per, unsigned nblocks) {
    __shared__ unsigned s_act[(MAX_ROWS + 4) * WX];
    __shared__ unsigned s_w1[MAX_ROWS * WX];
    __shared__ unsigned s_w2[MAX_ROWS * WX];
    __shared__ unsigned s_any;
    __shared__ unsigned s_gbase;

    const int tid  = threadIdx.x;
    const int bid  = blockIdx.x;
    const int lane = tid & 31;
    const int r0   = bid * rows_per;
    const int nrows  = min(H_IMG - r0, rows_per);
    const int nwords = nrows * WX;
    const int nquads = nrows * QX;

    float4* low4   = (float4*)out;
    float4* high4  = (float4*)(out + N_PIX);
    float4* final4 = (float4*)(out + 2 * N_PIX);

    const unsigned nsh   = (lane & 7u) * 4u;
    const unsigned gmask = 0xFFu << (lane & 24u);

    // cross-replay-safe barrier generation base (all blocks read before any
    // block can complete barrier 1, so this is race-free)
    if (tid == 0) s_gbase = g_release >> 1;

    for (int i = tid; i < (MAX_ROWS + 4) * WX; i += NT) s_act[i] = 0u;
    __syncthreads();
    unsigned gen = s_gbase;

    // -------- Phase 1: thresholds + masks --------
    for (int j = tid; j < nquads; j += NT) {
        int qg = r0 * QX + j;
        float4 v = __ldg(&thin4[qg]);
        float4 lo, hi;
        lo.x = (v.x < LOW_T)  ? 0.0f : v.x;  hi.x = (v.x < HIGH_T) ? 0.0f : v.x;
        lo.y = (v.y < LOW_T)  ? 0.0f : v.y;  hi.y = (v.y < HIGH_T) ? 0.0f : v.y;
        lo.z = (v.z < LOW_T)  ? 0.0f : v.z;  hi.z = (v.z < HIGH_T) ? 0.0f : v.z;
        lo.w = (v.w < LOW_T)  ? 0.0f : v.w;  hi.w = (v.w < HIGH_T) ? 0.0f : v.w;
        low4[qg]  = lo;
        high4[qg] = hi;

        unsigned nw = (v.x >= LOW_T ? 1u : 0u) | (v.y >= LOW_T ? 2u : 0u)
                    | (v.z >= LOW_T ? 4u : 0u) | (v.w >= LOW_T ? 8u : 0u);
        unsigned ns = (v.x >= HIGH_T ? 1u : 0u) | (v.y >= HIGH_T ? 2u : 0u)
                    | (v.z >= HIGH_T ? 4u : 0u) | (v.w >= HIGH_T ? 8u : 0u);
        unsigned wk = __reduce_or_sync(gmask, nw << nsh);
        unsigned ac = __reduce_or_sync(gmask, ns << nsh);

        if ((lane & 7) == 0) {
            int w  = j >> 3;
            int gw = r0 * WX + w;
            int r = gw >> 6, wx = gw & 63;
            unsigned t1c = (wx == 0) ? 0xFFFFFFFEu : (wx == WX - 1) ? 0x3FFFFFFFu : 0xFFFFFFFFu;
            unsigned t1r = (r >= 1 && r <= H_IMG - 3) ? 0xFFFFFFFFu : 0u;
            unsigned t2c = (wx == 0) ? 0xFFFFFFFCu : (wx == WX - 1) ? 0x1FFFFFFFu : 0xFFFFFFFFu;
            unsigned t2r = (r >= 2 && r <= H_IMG - 4) ? 0xFFFFFFFFu : 0u;
            s_w1[w] = wk & t1c & t1r;
            s_w2[w] = wk & t2c & t2r;
            s_act[((w >> 6) + 2) * WX + wx] = ac;
            __stcg(&g_active[gw], ac);
        }
    }

    // barrier 1 (publish masks/active)
    {
        gen++;
        __syncthreads();
        if (tid == 0) { __threadfence(); g_arrive[bid] = gen << 1; }
        if (bid == 0) {
            for (int b = tid; b < (int)nblocks; b += NT) {
                unsigned v;
                while (((v = g_arrive[b]) >> 1) < gen) __nanosleep(32);
            }
            __syncthreads();
            if (tid == 0) { __threadfence(); g_release = (gen << 1) | 1u; }
        }
        if (tid == 0) {
            while ((g_release >> 1) < gen) __nanosleep(32);
            __threadfence();
        }
        __syncthreads();
    }

    // -------- Phase 2: flood fill --------
    for (int pass = 0; pass < MAX_PASS; pass++) {
        for (int i = tid; i < 4 * WX; i += NT) {
            int hr = i >> 6, wx = i & 63;
            int gr = (hr < 2) ? (r0 - 2 + hr) : (r0 + nrows + (hr - 2));
            int sr = (hr < 2) ? hr : (nrows + hr);
            unsigned v = 0u;
            if ((unsigned)gr < (unsigned)H_IMG) v = __ldcg(&g_active[gr * WX + wx]);
            s_act[sr * WX + wx] = v;
        }
        __syncthreads();

        bool band_changed = false;
        for (;;) {
            bool ch = false;
            if (tid < nwords) {
                int wx = tid & 63;
                int sr = (tid >> 6) + 2;
                unsigned c  = s_act[sr * WX + wx];
                unsigned w1 = s_w1[tid];
                unsigned w2 = s_w2[tid];
                unsigned todo = (w1 | w2) & ~c;
                if (todo) {
                    auto S = [&](int r_, int x_) -> unsigned {
                        return ((unsigned)x_ < (unsigned)WX) ? s_act[r_ * WX + x_] : 0u;
                    };
                    unsigned l  = S(sr, wx - 1),      rr = S(sr, wx + 1);
                    unsigned u1 = S(sr - 1, wx), u1l = S(sr - 1, wx - 1), u1r = S(sr - 1, wx + 1);
                    unsigned d1 = S(sr + 1, wx), d1l = S(sr + 1, wx - 1), d1r = S(sr + 1, wx + 1);
                    unsigned conn1 =
                          u1 | __funnelshift_l(u1l, u1, 1) | __funnelshift_r(u1, u1r, 1)
                        |      __funnelshift_l(l,   c,  1) | __funnelshift_r(c,  rr,  1)
                        | d1 | __funnelshift_l(d1l, d1, 1) | __funnelshift_r(d1, d1r, 1);
                    unsigned nw2 = c | (w1 & conn1);
                    if (w2 & ~nw2) {
                        unsigned u2 = S(sr - 2, wx), u2l = S(sr - 2, wx - 1), u2r = S(sr - 2, wx + 1);
                        unsigned d2 = S(sr + 2, wx), d2l = S(sr + 2, wx - 1), d2r = S(sr + 2, wx + 1);
                        unsigned conn2 =
                              u2 | __funnelshift_l(u2l, u2, 2) | __funnelshift_r(u2, u2r, 2)
                            |      __funnelshift_l(l,   c,  2) | __funnelshift_r(c,  rr,  2)
                            | d2 | __funnelshift_l(d2l, d2, 2) | __funnelshift_r(d2, d2r, 2);
                        nw2 |= w2 & conn2;
                    }
                    #pragma unroll
                    for (int k = 0; k < 5; k++) {
                        unsigned sp = nw2;
                        nw2 |= (w1 & ((sp << 1) | (sp >> 1)))
                             | (w2 & ((sp << 2) | (sp >> 2)));
                    }
                    if (nw2 != c) { s_act[sr * WX + wx] = nw2; ch = true; }
                }
            }
            if (!__syncthreads_or(ch ? 1 : 0)) break;
            band_changed = true;
        }

        if (band_changed && tid < nwords)
            __stcg(&g_active[r0 * WX + tid],
                   s_act[((tid >> 6) + 2) * WX + (tid & 63)]);

        // grid barrier with embedded any-changed
        gen++;
        __syncthreads();
        if (tid == 0) {
            __threadfence();
            g_arrive[bid] = (gen << 1) | (band_changed ? 1u : 0u);
        }
        if (bid == 0) {
            unsigned myany = 0u;
            for (int b = tid; b < (int)nblocks; b += NT) {
                unsigned v;
                while (((v = g_arrive[b]) >> 1) < gen) __nanosleep(32);
                myany |= v & 1u;
            }
            unsigned any = __syncthreads_or(myany);
            if (tid == 0) { __threadfence(); g_release = (gen << 1) | any; }
        }
        if (tid == 0) {
            unsigned v;
            while (((v = g_release) >> 1) < gen) __nanosleep(32);
            s_any = v & 1u;
            __threadfence();
        }
        __syncthreads();
        if (!s_any) break;
    }

    // -------- Phase 3: final output --------
    for (int j = tid; j < nquads; j += NT) {
        int w = j >> 3;
        unsigned word = s_act[((w >> 6) + 2) * WX + (w & 63)];
        unsigned bits = word >> nsh;
        int qg = r0 * QX + j;
        float4 v = __ldg(&thin4[qg]);
        float4 f;
        f.x = (bits & 1u) ? v.x : 0.0f;
        f.y = (bits & 2u) ? v.y : 0.0f;
        f.z = (bits & 4u) ? v.z : 0.0f;
        f.w = (bits & 8u) ? v.w : 0.0f;
        final4[qg] = f;
    }
}

extern "C" void kernel_launch(void* const* d_in, const int* in_sizes, int n_in,
                              void* d_out, int out_size) {
    const float* thin = (const float*)d_in[0];
    float* out = (float*)d_out;
    (void)in_sizes; (void)n_in; (void)out_size;

    int dev = 0;
    cudaGetDevice(&dev);
    int nsm = 0;
    cudaDeviceGetAttribute(&nsm, cudaDevAttrMultiProcessorCount, dev);
    if (nsm <= 0) nsm = 148;
    int maxb = 0;
    cudaOccupancyMaxActiveBlocksPerMultiprocessor(&maxb, hyst_kernel, NT, 0);
    if (maxb < 1) maxb = 1;
    if (maxb > 2) maxb = 2;

    int capacity = nsm * maxb;
    int rows_per = (H_IMG + capacity - 1) / capacity;   // 7 (or 14 fallback)
    if (rows_per > MAX_ROWS) rows_per = MAX_ROWS;
    unsigned grid = (unsigned)((H_IMG + rows_per - 1) / rows_per);

    hyst_kernel<<<grid, NT>>>((const float4*)thin, out, rows_per, grid);
}